// round 2
// baseline (speedup 1.0000x reference)
#include <cuda_runtime.h>
#include <cstdint>

#define HEADS 3
#define HD 32
#define SEQ 343
#define BATCH 512
#define NW 64
#define CDIM 96
#define BN_ROWS (BATCH*SEQ)          /* 175616 */
#define PER (BATCH*HEADS*SEQ*HD)     /* 16859136 */
#define COMB_SZ (NW*HEADS*SEQ*SEQ)   /* 22596288 */
#define AO_SZ (2*BN_ROWS*CDIM)       /* 33718272 */

// Scratch (no allocations allowed) — __device__ globals:
__device__ __align__(256) float g_q[2][PER];   // [stream][b][h][n][d], q pre-scaled
__device__ __align__(256) float g_k[2][PER];
__device__ __align__(256) float g_v[2][PER];
__device__ __align__(256) float g_comb[COMB_SZ]; // mask[w,n,m] + bias[h,n,m]
__device__ __align__(256) float g_ao[AO_SZ];     // pre-projection attn out, [stream][b][n][c]

// ---------------------------------------------------------------------------
// comb[w,h,n,m] = mask[w,n,m] + bias_table[rel_index[n,m], h]
// ---------------------------------------------------------------------------
__global__ void comb_kernel(const float* __restrict__ mask,
                            const float* __restrict__ table,
                            const int* __restrict__ rel) {
    int idx = blockIdx.x * blockDim.x + threadIdx.x;
    if (idx >= COMB_SZ) return;
    int m = idx % SEQ;
    int t = idx / SEQ;
    int n = t % SEQ;
    t /= SEQ;
    int h = t % HEADS;
    int w = t / HEADS;
    g_comb[idx] = mask[((size_t)w * SEQ + n) * SEQ + m] + table[rel[n * SEQ + m] * HEADS + h];
}

// ---------------------------------------------------------------------------
// QKV GEMM: (175616 x 96) @ (96 x 288)^T + bias, scattered into q/k/v arrays
// blockIdx.y = which (0=q scaled, 1=k, 2=v). 64x96 output tile, 256 threads.
// ---------------------------------------------------------------------------
__global__ void qkv_kernel(const float* __restrict__ A,
                           const float* __restrict__ W,
                           const float* __restrict__ Wb,
                           int st) {
    __shared__ float Asm[64][33];
    __shared__ float Bsm[96][33];
    const int tid = threadIdx.x;
    const int which = blockIdx.y;
    const int row0 = blockIdx.x * 64;
    const int ty = tid >> 4, tx = tid & 15;

    float acc[4][6];
#pragma unroll
    for (int i = 0; i < 4; i++)
#pragma unroll
        for (int j = 0; j < 6; j++) acc[i][j] = 0.f;

    const int lr = tid >> 3;        // 0..31
    const int lc = (tid & 7) * 4;   // 0..28

    for (int kb = 0; kb < CDIM; kb += 32) {
#pragma unroll
        for (int rr = 0; rr < 64; rr += 32) {
            float4 va = *reinterpret_cast<const float4*>(A + (size_t)(row0 + lr + rr) * CDIM + kb + lc);
            Asm[lr + rr][lc] = va.x; Asm[lr + rr][lc + 1] = va.y;
            Asm[lr + rr][lc + 2] = va.z; Asm[lr + rr][lc + 3] = va.w;
        }
#pragma unroll
        for (int rr = 0; rr < 96; rr += 32) {
            float4 vb = *reinterpret_cast<const float4*>(W + (size_t)(which * 96 + lr + rr) * CDIM + kb + lc);
            Bsm[lr + rr][lc] = vb.x; Bsm[lr + rr][lc + 1] = vb.y;
            Bsm[lr + rr][lc + 2] = vb.z; Bsm[lr + rr][lc + 3] = vb.w;
        }
        __syncthreads();
#pragma unroll
        for (int kk = 0; kk < 32; kk++) {
            float a[4], bb[6];
#pragma unroll
            for (int i = 0; i < 4; i++) a[i] = Asm[ty * 4 + i][kk];
#pragma unroll
            for (int j = 0; j < 6; j++) bb[j] = Bsm[tx * 6 + j][kk];
#pragma unroll
            for (int i = 0; i < 4; i++)
#pragma unroll
                for (int j = 0; j < 6; j++)
                    acc[i][j] = fmaf(a[i], bb[j], acc[i][j]);
        }
        __syncthreads();
    }

    const float scale = (which == 0) ? 0.17677669529663687f : 1.0f;  // 32^-0.5
    float* dst = (which == 0) ? g_q[st] : ((which == 1) ? g_k[st] : g_v[st]);
#pragma unroll
    for (int i = 0; i < 4; i++) {
        int bn = row0 + ty * 4 + i;
        int b = bn / SEQ, n = bn - b * SEQ;
#pragma unroll
        for (int j = 0; j < 6; j++) {
            int jl = tx * 6 + j;
            int h = jl >> 5, d = jl & 31;
            float v = (acc[i][j] + Wb[which * 96 + jl]) * scale;
            dst[(((size_t)b * HEADS + h) * SEQ + n) * HD + d] = v;
        }
    }
}

// ---------------------------------------------------------------------------
// Attention, single-pass online softmax (flash-style).
// Block = 32 query rows x (b,h) x stream, 256 threads, ~30 KB static smem.
// Per 64-key tile: S = QK^T + comb -> online max/sum update -> acc = acc*f + e@V
// ---------------------------------------------------------------------------
__global__ void __launch_bounds__(256) attn_kernel() {
    __shared__ float Qs[32 * 33];
    __shared__ float Ks[64 * 33];
    __shared__ float Vs[64 * 33];
    __shared__ float Stile[32 * 65];
    __shared__ float rowm[32], rowl[32], rowf[32];

    const int tid = threadIdx.x;
    const int q0 = blockIdx.x * 32;
    const int bh = blockIdx.y;      // b*3 + h
    const int st = blockIdx.z;
    const int b = bh / HEADS, h = bh - b * HEADS;
    const int w = b & (NW - 1);

    // Cross streams: st=0 -> Q from x, K/V from x1; st=1 -> Q from x1, K/V from x
    const float* Qp = g_q[st]     + (size_t)bh * (SEQ * HD);
    const float* Kp = g_k[1 - st] + (size_t)bh * (SEQ * HD);
    const float* Vp = g_v[1 - st] + (size_t)bh * (SEQ * HD);
    const float* cb = g_comb + ((size_t)(w * HEADS + h) * SEQ + q0) * SEQ;

    if (tid < 32) { rowm[tid] = -1e30f; rowl[tid] = 0.f; }
    for (int idx = tid; idx < 32 * 32; idx += 256) {
        int i = idx >> 5, d = idx & 31;
        int n = q0 + i;
        Qs[i * 33 + d] = (n < SEQ) ? Qp[n * HD + d] : 0.f;
    }

    // PV accumulator: thread (d = tid&31, rowgroup = tid>>5) owns 4 rows at dim d
    const int dA = tid & 31, tyA = tid >> 5;
    float acc[4] = {0.f, 0.f, 0.f, 0.f};

    const int tyS = tid >> 6, txS = tid & 63;   // score mapping: 8 rows x 1 col
    const int rowR = tid >> 3, subR = tid & 7;  // reduce mapping: 1 row x 8 cols

    for (int kb = 0; kb < SEQ; kb += 64) {
        __syncthreads();   // protect Ks/Vs/Stile from previous iteration readers
        // ---- stage K,V tiles ----
        for (int idx = tid; idx < 64 * 32; idx += 256) {
            int m = idx >> 5, d = idx & 31;
            int gm = kb + m;
            float kv = (gm < SEQ) ? Kp[gm * HD + d] : 0.f;
            float vv = (gm < SEQ) ? Vp[gm * HD + d] : 0.f;
            Ks[m * 33 + d] = kv;
            Vs[m * 33 + d] = vv;
        }
        __syncthreads();

        // ---- scores: S = Q K^T + comb ----
        {
            float sc[8];
#pragma unroll
            for (int r = 0; r < 8; r++) sc[r] = 0.f;
#pragma unroll
            for (int d = 0; d < HD; d++) {
                float kd = Ks[txS * 33 + d];
#pragma unroll
                for (int r = 0; r < 8; r++)
                    sc[r] = fmaf(Qs[(tyS + 4 * r) * 33 + d], kd, sc[r]);
            }
            int m = kb + txS;
#pragma unroll
            for (int r = 0; r < 8; r++) {
                int i = tyS + 4 * r;
                float val;
                if (m < SEQ)
                    val = sc[r] + ((q0 + i < SEQ) ? cb[(size_t)i * SEQ + m] : 0.f);
                else
                    val = -1e30f;
                Stile[i * 65 + txS] = val;
            }
        }
        __syncthreads();

        // ---- online softmax update (8 threads per row) ----
        {
            float tm = -1e30f;
#pragma unroll
            for (int c = subR; c < 64; c += 8) tm = fmaxf(tm, Stile[rowR * 65 + c]);
#pragma unroll
            for (int o = 4; o > 0; o >>= 1) tm = fmaxf(tm, __shfl_xor_sync(0xffffffffu, tm, o));
            float oldm = rowm[rowR];
            float nm = fmaxf(oldm, tm);
            float ts = 0.f;
#pragma unroll
            for (int c = subR; c < 64; c += 8) {
                float e = __expf(Stile[rowR * 65 + c] - nm);
                Stile[rowR * 65 + c] = e;
                ts += e;
            }
#pragma unroll
            for (int o = 4; o > 0; o >>= 1) ts += __shfl_xor_sync(0xffffffffu, ts, o);
            if (subR == 0) {
                float f = __expf(oldm - nm);
                rowf[rowR] = f;
                rowl[rowR] = rowl[rowR] * f + ts;
                rowm[rowR] = nm;
            }
        }
        __syncthreads();

        // ---- acc = acc * f + e @ V ----
        {
#pragma unroll
            for (int rr = 0; rr < 4; rr++) {
                int i = tyA * 4 + rr;
                float a = acc[rr] * rowf[i];
#pragma unroll 8
                for (int m2 = 0; m2 < 64; m2++)
                    a = fmaf(Stile[i * 65 + m2], Vs[m2 * 33 + dA], a);
                acc[rr] = a;
            }
        }
    }

    // ---- write normalized output ----
#pragma unroll
    for (int rr = 0; rr < 4; rr++) {
        int i = tyA * 4 + rr;
        int n = q0 + i;
        if (n < SEQ) {
            g_ao[(size_t)st * ((size_t)BN_ROWS * CDIM) +
                 ((size_t)b * SEQ + n) * CDIM + h * HD + dA] = acc[rr] / rowl[i];
        }
    }
}

// ---------------------------------------------------------------------------
// Output projection: (2*175616 x 96) @ (96 x 96)^T + bias -> d_out
// ---------------------------------------------------------------------------
__global__ void proj_kernel(const float* __restrict__ W,
                            const float* __restrict__ Wb,
                            float* __restrict__ out) {
    __shared__ float Asm[64][33];
    __shared__ float Bsm[96][33];
    const int tid = threadIdx.x;
    const int row0 = blockIdx.x * 64;
    const int ty = tid >> 4, tx = tid & 15;

    float acc[4][6];
#pragma unroll
    for (int i = 0; i < 4; i++)
#pragma unroll
        for (int j = 0; j < 6; j++) acc[i][j] = 0.f;

    const int lr = tid >> 3;
    const int lc = (tid & 7) * 4;

    for (int kb = 0; kb < CDIM; kb += 32) {
#pragma unroll
        for (int rr = 0; rr < 64; rr += 32) {
            float4 va = *reinterpret_cast<const float4*>(g_ao + (size_t)(row0 + lr + rr) * CDIM + kb + lc);
            Asm[lr + rr][lc] = va.x; Asm[lr + rr][lc + 1] = va.y;
            Asm[lr + rr][lc + 2] = va.z; Asm[lr + rr][lc + 3] = va.w;
        }
#pragma unroll
        for (int rr = 0; rr < 96; rr += 32) {
            float4 vb = *reinterpret_cast<const float4*>(W + (size_t)(lr + rr) * CDIM + kb + lc);
            Bsm[lr + rr][lc] = vb.x; Bsm[lr + rr][lc + 1] = vb.y;
            Bsm[lr + rr][lc + 2] = vb.z; Bsm[lr + rr][lc + 3] = vb.w;
        }
        __syncthreads();
#pragma unroll
        for (int kk = 0; kk < 32; kk++) {
            float a[4], bb[6];
#pragma unroll
            for (int i = 0; i < 4; i++) a[i] = Asm[ty * 4 + i][kk];
#pragma unroll
            for (int j = 0; j < 6; j++) bb[j] = Bsm[tx * 6 + j][kk];
#pragma unroll
            for (int i = 0; i < 4; i++)
#pragma unroll
                for (int j = 0; j < 6; j++)
                    acc[i][j] = fmaf(a[i], bb[j], acc[i][j]);
        }
        __syncthreads();
    }

#pragma unroll
    for (int i = 0; i < 4; i++) {
        size_t bn = row0 + ty * 4 + i;
#pragma unroll
        for (int j = 0; j < 6; j++) {
            int jl = tx * 6 + j;
            out[bn * CDIM + jl] = acc[i][j] + Wb[jl];
        }
    }
}

// ---------------------------------------------------------------------------
extern "C" void kernel_launch(void* const* d_in, const int* in_sizes, int n_in,
                              void* d_out, int out_size) {
    const float* x    = (const float*)d_in[0];
    const float* x1   = (const float*)d_in[1];
    const float* mask = (const float*)d_in[2];
    const float* qw   = (const float*)d_in[3];
    const float* qb   = (const float*)d_in[4];
    const float* pw   = (const float*)d_in[5];
    const float* pb   = (const float*)d_in[6];
    const float* bt   = (const float*)d_in[7];
    const int*   ri   = (const int*)d_in[8];
    float* out = (float*)d_out;

    // combined additive term (L2-resident during attention)
    comb_kernel<<<(COMB_SZ + 255) / 256, 256>>>(mask, bt, ri);

    // QKV for both streams
    dim3 gq(BN_ROWS / 64, 3);
    qkv_kernel<<<gq, 256>>>(x,  qw, qb, 0);
    qkv_kernel<<<gq, 256>>>(x1, qw, qb, 1);

    // attention — static smem only (~30 KB), no attribute calls needed
    dim3 ga((SEQ + 31) / 32, BATCH * HEADS, 2);
    attn_kernel<<<ga, 256>>>();

    // output projection for both streams (contiguous -> d_out = [out; out_m])
    proj_kernel<<<(2 * BN_ROWS) / 64, 256>>>(pw, pb, out);
}

// round 3
// speedup vs baseline: 1.4739x; 1.4739x over previous
#include <cuda_runtime.h>
#include <cstdint>

#define HEADS 3
#define HD 32
#define SEQ 343
#define BATCH 512
#define NW 64
#define CDIM 96
#define BN_ROWS (BATCH*SEQ)          /* 175616 */
#define PER (BATCH*HEADS*SEQ*HD)     /* 16859136 */
#define COMB_SZ (NW*HEADS*SEQ*SEQ)   /* 22596288 */
#define AO_SZ (2*BN_ROWS*CDIM)       /* 33718272 */

// Scratch (no allocations allowed) — __device__ globals:
__device__ __align__(256) float g_q[2][PER];   // [stream][b][h][n][d], q pre-scaled
__device__ __align__(256) float g_k[2][PER];
__device__ __align__(256) float g_v[2][PER];
__device__ __align__(256) float g_comb[COMB_SZ]; // mask[w,n,m] + bias[h,n,m]
__device__ __align__(256) float g_ao[AO_SZ];     // pre-projection attn out, [stream][b][n][c]

// ---------------------------------------------------------------------------
// comb[w,h,n,m] = mask[w,n,m] + bias_table[rel_index[n,m], h]
// ---------------------------------------------------------------------------
__global__ void comb_kernel(const float* __restrict__ mask,
                            const float* __restrict__ table,
                            const int* __restrict__ rel) {
    int idx = blockIdx.x * blockDim.x + threadIdx.x;
    if (idx >= COMB_SZ) return;
    int m = idx % SEQ;
    int t = idx / SEQ;
    int n = t % SEQ;
    t /= SEQ;
    int h = t % HEADS;
    int w = t / HEADS;
    g_comb[idx] = mask[((size_t)w * SEQ + n) * SEQ + m] + table[rel[n * SEQ + m] * HEADS + h];
}

// ---------------------------------------------------------------------------
// QKV GEMM: (175616 x 96) @ (96 x 288)^T + bias, scattered into q/k/v arrays
// blockIdx.y = which (0=q scaled, 1=k, 2=v). 64x96 output tile, 256 threads.
// ---------------------------------------------------------------------------
__global__ void qkv_kernel(const float* __restrict__ A,
                           const float* __restrict__ W,
                           const float* __restrict__ Wb,
                           int st) {
    __shared__ float Asm[64][33];
    __shared__ float Bsm[96][33];
    const int tid = threadIdx.x;
    const int which = blockIdx.y;
    const int row0 = blockIdx.x * 64;
    const int ty = tid >> 4, tx = tid & 15;

    float acc[4][6];
#pragma unroll
    for (int i = 0; i < 4; i++)
#pragma unroll
        for (int j = 0; j < 6; j++) acc[i][j] = 0.f;

    const int lr = tid >> 3;        // 0..31
    const int lc = (tid & 7) * 4;   // 0..28

    for (int kb = 0; kb < CDIM; kb += 32) {
#pragma unroll
        for (int rr = 0; rr < 64; rr += 32) {
            float4 va = *reinterpret_cast<const float4*>(A + (size_t)(row0 + lr + rr) * CDIM + kb + lc);
            Asm[lr + rr][lc] = va.x; Asm[lr + rr][lc + 1] = va.y;
            Asm[lr + rr][lc + 2] = va.z; Asm[lr + rr][lc + 3] = va.w;
        }
#pragma unroll
        for (int rr = 0; rr < 96; rr += 32) {
            float4 vb = *reinterpret_cast<const float4*>(W + (size_t)(which * 96 + lr + rr) * CDIM + kb + lc);
            Bsm[lr + rr][lc] = vb.x; Bsm[lr + rr][lc + 1] = vb.y;
            Bsm[lr + rr][lc + 2] = vb.z; Bsm[lr + rr][lc + 3] = vb.w;
        }
        __syncthreads();
#pragma unroll
        for (int kk = 0; kk < 32; kk++) {
            float a[4], bb[6];
#pragma unroll
            for (int i = 0; i < 4; i++) a[i] = Asm[ty * 4 + i][kk];
#pragma unroll
            for (int j = 0; j < 6; j++) bb[j] = Bsm[tx * 6 + j][kk];
#pragma unroll
            for (int i = 0; i < 4; i++)
#pragma unroll
                for (int j = 0; j < 6; j++)
                    acc[i][j] = fmaf(a[i], bb[j], acc[i][j]);
        }
        __syncthreads();
    }

    const float scale = (which == 0) ? 0.17677669529663687f : 1.0f;  // 32^-0.5
    float* dst = (which == 0) ? g_q[st] : ((which == 1) ? g_k[st] : g_v[st]);
#pragma unroll
    for (int i = 0; i < 4; i++) {
        int bn = row0 + ty * 4 + i;
        int b = bn / SEQ, n = bn - b * SEQ;
#pragma unroll
        for (int j = 0; j < 6; j++) {
            int jl = tx * 6 + j;
            int h = jl >> 5, d = jl & 31;
            float v = (acc[i][j] + Wb[which * 96 + jl]) * scale;
            dst[(((size_t)b * HEADS + h) * SEQ + n) * HD + d] = v;
        }
    }
}

// ---------------------------------------------------------------------------
// Attention, single-pass online softmax (flash-style).
// Block = 64 query rows x (b,h) x stream, 256 threads, 42 KB static smem.
// Score phase: 4x4 register tile (0.5 smem values/FMA).
// PV phase:    4 rows x 2 dims per thread (0.75 values/FMA).
// ---------------------------------------------------------------------------
__global__ void __launch_bounds__(256) attn_kernel() {
    __shared__ float Qs[64 * 33];
    __shared__ float Ks[64 * 33];
    __shared__ float Vs[64 * 34];
    __shared__ float Stile[64 * 65];
    __shared__ float rowm[64], rowl[64], rowf[64];

    const int tid = threadIdx.x;
    const int q0 = blockIdx.x * 64;
    const int bh = blockIdx.y;      // b*3 + h
    const int st = blockIdx.z;
    const int b = bh / HEADS, h = bh - b * HEADS;
    const int w = b & (NW - 1);

    // Cross streams: st=0 -> Q from x, K/V from x1; st=1 -> Q from x1, K/V from x
    const float* Qp = g_q[st]     + (size_t)bh * (SEQ * HD);
    const float* Kp = g_k[1 - st] + (size_t)bh * (SEQ * HD);
    const float* Vp = g_v[1 - st] + (size_t)bh * (SEQ * HD);
    const float* cb = g_comb + ((size_t)(w * HEADS + h) * SEQ + q0) * SEQ;

    if (tid < 64) { rowm[tid] = -1e30f; rowl[tid] = 0.f; }
    for (int idx = tid; idx < 64 * 32; idx += 256) {
        int i = idx >> 5, d = idx & 31;
        int n = q0 + i;
        Qs[i * 33 + d] = (n < SEQ) ? Qp[n * HD + d] : 0.f;
    }

    // Score-phase thread tile: rg (rows) x cg (cols), each 4x4
    const int rg = tid >> 4, cg = tid & 15;
    // Softmax mapping: 4 threads per row
    const int rowR = tid >> 2, subR = tid & 3;
    // PV mapping: rows rg2*4.., dims d0 = dg*2
    const int rg2 = tid >> 4, dg = tid & 15, d0 = dg * 2;

    float acc0[4], acc1[4];   // PV accumulators (4 rows x 2 dims)
#pragma unroll
    for (int r = 0; r < 4; r++) { acc0[r] = 0.f; acc1[r] = 0.f; }

    for (int kb = 0; kb < 384; kb += 64) {
        __syncthreads();   // protect Ks/Vs/Stile from previous iteration readers
        // ---- stage K,V tiles ----
        for (int idx = tid; idx < 64 * 32; idx += 256) {
            int m = idx >> 5, d = idx & 31;
            int gm = kb + m;
            float kv = (gm < SEQ) ? Kp[gm * HD + d] : 0.f;
            float vv = (gm < SEQ) ? Vp[gm * HD + d] : 0.f;
            Ks[m * 33 + d] = kv;
            Vs[m * 34 + d] = vv;
        }
        __syncthreads();

        // ---- scores: S = Q K^T + comb (4x4 register tile) ----
        {
            float sc[4][4];
#pragma unroll
            for (int i = 0; i < 4; i++)
#pragma unroll
                for (int j = 0; j < 4; j++) sc[i][j] = 0.f;
#pragma unroll
            for (int d = 0; d < HD; d++) {
                float qv[4], kv[4];
#pragma unroll
                for (int i = 0; i < 4; i++) qv[i] = Qs[(rg * 4 + i) * 33 + d];
#pragma unroll
                for (int j = 0; j < 4; j++) kv[j] = Ks[(cg * 4 + j) * 33 + d];
#pragma unroll
                for (int i = 0; i < 4; i++)
#pragma unroll
                    for (int j = 0; j < 4; j++)
                        sc[i][j] = fmaf(qv[i], kv[j], sc[i][j]);
            }
#pragma unroll
            for (int i = 0; i < 4; i++) {
                int gi = rg * 4 + i;
                bool qok = (q0 + gi) < SEQ;
#pragma unroll
                for (int j = 0; j < 4; j++) {
                    int lm = cg * 4 + j;
                    int m = kb + lm;
                    float val;
                    if (m >= SEQ) val = -1e30f;
                    else if (qok) val = sc[i][j] + cb[(size_t)gi * SEQ + m];
                    else val = sc[i][j];
                    Stile[gi * 65 + lm] = val;
                }
            }
        }
        __syncthreads();

        // ---- online softmax update (4 threads per row, 16 cols each) ----
        {
            float tm = -1e30f;
#pragma unroll
            for (int c = subR; c < 64; c += 4) tm = fmaxf(tm, Stile[rowR * 65 + c]);
#pragma unroll
            for (int o = 2; o > 0; o >>= 1) tm = fmaxf(tm, __shfl_xor_sync(0xffffffffu, tm, o));
            float oldm = rowm[rowR];
            float nm = fmaxf(oldm, tm);
            float ts = 0.f;
#pragma unroll
            for (int c = subR; c < 64; c += 4) {
                float e = __expf(Stile[rowR * 65 + c] - nm);
                Stile[rowR * 65 + c] = e;
                ts += e;
            }
#pragma unroll
            for (int o = 2; o > 0; o >>= 1) ts += __shfl_xor_sync(0xffffffffu, ts, o);
            if (subR == 0) {
                float f = __expf(oldm - nm);
                rowf[rowR] = f;
                rowl[rowR] = rowl[rowR] * f + ts;
                rowm[rowR] = nm;
            }
        }
        __syncthreads();

        // ---- acc = acc * f + P @ V  (4 rows x 2 dims per thread) ----
        {
            float f0 = rowf[rg2 * 4 + 0];
            float f1 = rowf[rg2 * 4 + 1];
            float f2 = rowf[rg2 * 4 + 2];
            float f3 = rowf[rg2 * 4 + 3];
            acc0[0] *= f0; acc1[0] *= f0;
            acc0[1] *= f1; acc1[1] *= f1;
            acc0[2] *= f2; acc1[2] *= f2;
            acc0[3] *= f3; acc1[3] *= f3;
#pragma unroll 8
            for (int m2 = 0; m2 < 64; m2++) {
                float v0 = Vs[m2 * 34 + d0];
                float v1 = Vs[m2 * 34 + d0 + 1];
#pragma unroll
                for (int r = 0; r < 4; r++) {
                    float s = Stile[(rg2 * 4 + r) * 65 + m2];
                    acc0[r] = fmaf(s, v0, acc0[r]);
                    acc1[r] = fmaf(s, v1, acc1[r]);
                }
            }
        }
    }

    // ---- write normalized output ----
#pragma unroll
    for (int r = 0; r < 4; r++) {
        int i = rg2 * 4 + r;
        int n = q0 + i;
        if (n < SEQ) {
            float inv = 1.0f / rowl[i];
            size_t base = (size_t)st * ((size_t)BN_ROWS * CDIM) +
                          ((size_t)b * SEQ + n) * CDIM + h * HD + d0;
            g_ao[base]     = acc0[r] * inv;
            g_ao[base + 1] = acc1[r] * inv;
        }
    }
}

// ---------------------------------------------------------------------------
// Output projection: (2*175616 x 96) @ (96 x 96)^T + bias -> d_out
// ---------------------------------------------------------------------------
__global__ void proj_kernel(const float* __restrict__ W,
                            const float* __restrict__ Wb,
                            float* __restrict__ out) {
    __shared__ float Asm[64][33];
    __shared__ float Bsm[96][33];
    const int tid = threadIdx.x;
    const int row0 = blockIdx.x * 64;
    const int ty = tid >> 4, tx = tid & 15;

    float acc[4][6];
#pragma unroll
    for (int i = 0; i < 4; i++)
#pragma unroll
        for (int j = 0; j < 6; j++) acc[i][j] = 0.f;

    const int lr = tid >> 3;
    const int lc = (tid & 7) * 4;

    for (int kb = 0; kb < CDIM; kb += 32) {
#pragma unroll
        for (int rr = 0; rr < 64; rr += 32) {
            float4 va = *reinterpret_cast<const float4*>(g_ao + (size_t)(row0 + lr + rr) * CDIM + kb + lc);
            Asm[lr + rr][lc] = va.x; Asm[lr + rr][lc + 1] = va.y;
            Asm[lr + rr][lc + 2] = va.z; Asm[lr + rr][lc + 3] = va.w;
        }
#pragma unroll
        for (int rr = 0; rr < 96; rr += 32) {
            float4 vb = *reinterpret_cast<const float4*>(W + (size_t)(lr + rr) * CDIM + kb + lc);
            Bsm[lr + rr][lc] = vb.x; Bsm[lr + rr][lc + 1] = vb.y;
            Bsm[lr + rr][lc + 2] = vb.z; Bsm[lr + rr][lc + 3] = vb.w;
        }
        __syncthreads();
#pragma unroll
        for (int kk = 0; kk < 32; kk++) {
            float a[4], bb[6];
#pragma unroll
            for (int i = 0; i < 4; i++) a[i] = Asm[ty * 4 + i][kk];
#pragma unroll
            for (int j = 0; j < 6; j++) bb[j] = Bsm[tx * 6 + j][kk];
#pragma unroll
            for (int i = 0; i < 4; i++)
#pragma unroll
                for (int j = 0; j < 6; j++)
                    acc[i][j] = fmaf(a[i], bb[j], acc[i][j]);
        }
        __syncthreads();
    }

#pragma unroll
    for (int i = 0; i < 4; i++) {
        size_t bn = row0 + ty * 4 + i;
#pragma unroll
        for (int j = 0; j < 6; j++) {
            int jl = tx * 6 + j;
            out[bn * CDIM + jl] = acc[i][j] + Wb[jl];
        }
    }
}

// ---------------------------------------------------------------------------
extern "C" void kernel_launch(void* const* d_in, const int* in_sizes, int n_in,
                              void* d_out, int out_size) {
    const float* x    = (const float*)d_in[0];
    const float* x1   = (const float*)d_in[1];
    const float* mask = (const float*)d_in[2];
    const float* qw   = (const float*)d_in[3];
    const float* qb   = (const float*)d_in[4];
    const float* pw   = (const float*)d_in[5];
    const float* pb   = (const float*)d_in[6];
    const float* bt   = (const float*)d_in[7];
    const int*   ri   = (const int*)d_in[8];
    float* out = (float*)d_out;

    // combined additive term (L2-resident during attention)
    comb_kernel<<<(COMB_SZ + 255) / 256, 256>>>(mask, bt, ri);

    // QKV for both streams
    dim3 gq(BN_ROWS / 64, 3);
    qkv_kernel<<<gq, 256>>>(x,  qw, qb, 0);
    qkv_kernel<<<gq, 256>>>(x1, qw, qb, 1);

    // attention — 64-row q-tiles, static smem only (42 KB)
    dim3 ga((SEQ + 63) / 64, BATCH * HEADS, 2);
    attn_kernel<<<ga, 256>>>();

    // output projection for both streams (contiguous -> d_out = [out; out_m])
    proj_kernel<<<(2 * BN_ROWS) / 64, 256>>>(pw, pb, out);
}